// round 10
// baseline (speedup 1.0000x reference)
#include <cuda_runtime.h>
#include <cstdint>

// Problem constants (fixed by the dataset)
#define B_    4
#define N_    8192
#define M_    2048
#define K_    32
#define C_    64
#define NBINS 16

#define MPB     8     // m-rows per block, one warp per row (warp-autonomous)
#define THREADS 256

#define G_STRIDE 36   // floats per (m,k) g-record: 32 data + 4 pad

typedef unsigned long long ull;

__device__ int g_idx_is64;

// Detect whether nn_index buffer is int64 or int32 (values < 8192 => high
// words of int64 all zero; int32 data makes odd words random). Deterministic.
__global__ void detect_idx_dtype_kernel(const int* __restrict__ words) {
    __shared__ int any_nonzero;
    if (threadIdx.x == 0) any_nonzero = 0;
    __syncthreads();
    int local = 0;
    for (int i = threadIdx.x; i < 2048; i += blockDim.x) {
        if (words[2 * i + 1] != 0) local = 1;
    }
    if (local) atomicOr(&any_nonzero, 1);
    __syncthreads();
    if (threadIdx.x == 0) g_idx_is64 = any_nonzero ? 0 : 1;
}

// Packed fp32x2 ops (Blackwell): one instruction, two fp32 lanes.
#define FMA2(d, a, b, c) \
    asm("fma.rn.f32x2 %0, %1, %2, %3;" : "=l"(d) : "l"(a), "l"(b), "l"(c))
#define ADD2(d, a, b) \
    asm("add.rn.f32x2 %0, %1, %2;" : "=l"(d) : "l"(a), "l"(b))

__global__ __launch_bounds__(THREADS, 4) void fuzzy_sphere_kernel(
    const float* __restrict__ database,      // (B, N, 3)
    const float* __restrict__ query,         // (B, M, 3)
    const void*  __restrict__ nn_index_raw,  // (B, M, K) int64 or int32
    const float* __restrict__ nn_dist,       // (B, M, K)
    const float* __restrict__ feats,         // (B, N, C)
    const float* __restrict__ fw,            // (NBINS, C, 1)
    float* __restrict__ out)                 // (B, M, C)
{
    __shared__ float sg[MPB * K_ * G_STRIDE];  // duplicated g-pairs, 36.9 KB

    const int tid  = threadIdx.x;
    const int lane = tid & 31;
    const int wid  = tid >> 5;                 // warp id == m-row within block
    const int t2   = lane * 2;                 // channel pair base
    const int gm0  = blockIdx.x * MPB;
    const int gm   = gm0 + wid;                // this warp's flattened row
    const int is64 = g_idx_is64;

    // ---------------- Phase 1: warp = row, lane = k --------------------------
    // Each lane computes the 16 factorized bin coefficients g for (row, k=lane)
    // and keeps the feature-row offset in a REGISTER (shfl'd in phase 2).
    int off_reg;
    {
        const int k = lane;
        const int b = gm >> 11;             // gm / M_

        int nidx;
        if (is64) nidx = (int)((const long long*)nn_index_raw)[(size_t)gm * K_ + k];
        else      nidx = ((const int*)nn_index_raw)[(size_t)gm * K_ + k];

        const float d  = nn_dist[(size_t)gm * K_ + k];
        const float qx = query[gm * 3 + 0];
        const float qy = query[gm * 3 + 1];
        const float qz = query[gm * 3 + 2];
        const float* dbp = database + ((size_t)b * N_ + nidx) * 3;
        const float x = dbp[0] - qx;
        const float y = dbp[1] - qy;
        const float z = dbp[2] - qz;

        const float azimuth = atan2f(y, x) + 3.14159265358979323846f;
        float ct = z / (d + 1e-8f);
        ct = fminf(fmaxf(ct, -1.0f), 1.0f);
        const float elevation = acosf(ct);

        const float SC = 0.63661977236758134f;   // 4/(2pi) == 2/pi
        const float ab = azimuth   * SC;
        const float eb = elevation * SC;
        float rb = d / 0.05f;
        rb = fminf(fmaxf(rb, 0.0f), 2.0f - 1e-6f);

        const float afl = floorf(ab), efl = floorf(eb), rfl = floorf(rb);
        const float afr = ab - afl,   efr = eb - efl,   rfr = rb - rfl;
        const float ai = 1.0f - afr,  ei = 1.0f - efr,  ri = 1.0f - rfr;

        const int a0 = ((int)afl) & 3;
        const int ef = (int)efl;             // 0,1,(2 at poles)
        const int rf = (int)rfl;             // 0 or 1

        // Factorized axis coefficients (exact: ei+efr == 1, ri+rfr == 1)
        const float FE0 = (ef == 0) ? ei  : 0.0f;
        const float FE1 = (ef == 0) ? efr : 1.0f;
        const float FR0 = (rf == 0) ? ri  : 0.0f;
        const float FR1 = (rf == 0) ? rfr : 1.0f;

        const float t00 = FE0 * FR0, t01 = FE0 * FR1;
        const float t10 = FE1 * FR0, t11 = FE1 * FR1;

        // FA[A]: ai at a0, afr at (a0+1)&3, else 0 — no dynamic indexing
        const float fa0 = (a0 == 0) ? ai : ((a0 == 3) ? afr : 0.0f);
        const float fa1 = (a0 == 1) ? ai : ((a0 == 0) ? afr : 0.0f);
        const float fa2 = (a0 == 2) ? ai : ((a0 == 1) ? afr : 0.0f);
        const float fa3 = (a0 == 3) ? ai : ((a0 == 2) ? afr : 0.0f);

        float* dst = sg + (wid * K_ + k) * G_STRIDE;
        const float fa[4] = {fa0, fa1, fa2, fa3};
        #pragma unroll
        for (int A = 0; A < 4; A++) {
            const float g00 = fa[A] * t00, g01 = fa[A] * t01;
            const float g10 = fa[A] * t10, g11 = fa[A] * t11;
            ((float4*)dst)[2 * A + 0] = make_float4(g00, g00, g01, g01);
            ((float4*)dst)[2 * A + 1] = make_float4(g10, g10, g11, g11);
        }

        off_reg = (b * N_ + nidx) * C_;
    }
    // Warp-internal producer/consumer only — no block barrier needed.
    __syncwarp();

    // ---------------- Phase 2: sum-interchanged accumulation -----------------
    // s[j] = sum_k g[k,j] * nf[k]  (16 independent f32x2 accumulators)
    const float* mygd = sg + wid * K_ * G_STRIDE;

    ull s[NBINS];
    #pragma unroll
    for (int j = 0; j < NBINS; j++) s[j] = 0;

    // 4-deep software pipeline for the gathered feature loads.
    ull nfp[4];
    #pragma unroll
    for (int k = 0; k < 4; k++) {
        const int off = __shfl_sync(0xffffffffu, off_reg, k);
        nfp[k] = *(const ull*)(feats + off + t2);
    }

    #pragma unroll 4
    for (int k = 0; k < K_; k++) {
        const ull nf = nfp[k & 3];
        if (k + 4 < K_) {
            const int off = __shfl_sync(0xffffffffu, off_reg, k + 4);
            nfp[k & 3] = *(const ull*)(feats + off + t2);
        }

        // 16 duplicated g-pairs for this k (8 broadcast LDS.128)
        const ulonglong2* gp = (const ulonglong2*)(mygd + k * G_STRIDE);
        #pragma unroll
        for (int j = 0; j < 8; j++) {
            const ulonglong2 ua = gp[j];
            FMA2(s[2 * j + 0], ua.x, nf, s[2 * j + 0]);
            FMA2(s[2 * j + 1], ua.y, nf, s[2 * j + 1]);
        }
    }

    // ---------------- Epilogue: apply weights once per row -------------------
    // out[c] = sum_j w[j,c] * s[j]; coalesced 8B loads from fw (L2/L1-hot).
    ull acc0 = 0, acc1 = 0;
    #pragma unroll
    for (int j = 0; j < NBINS; j += 2) {
        const ull w0 = *(const ull*)(fw + (j + 0) * C_ + t2);
        const ull w1 = *(const ull*)(fw + (j + 1) * C_ + t2);
        FMA2(acc0, w0, s[j + 0], acc0);
        FMA2(acc1, w1, s[j + 1], acc1);
    }
    ull acc;
    ADD2(acc, acc0, acc1);

    *(ull*)(out + (size_t)gm * C_ + t2) = acc;
}

extern "C" void kernel_launch(void* const* d_in, const int* in_sizes, int n_in,
                              void* d_out, int out_size) {
    const float* database = (const float*)d_in[0];
    const float* query    = (const float*)d_in[1];
    const void*  nn_index = (const void*) d_in[2];
    // d_in[3] = nn_count (unused by the reference einsum)
    const float* nn_dist  = (const float*)d_in[4];
    const float* feats    = (const float*)d_in[5];
    const float* fw       = (const float*)d_in[6];
    float* out = (float*)d_out;

    detect_idx_dtype_kernel<<<1, 256>>>((const int*)nn_index);

    const int blocks = (B_ * M_) / MPB;   // 1024
    fuzzy_sphere_kernel<<<blocks, THREADS>>>(
        database, query, nn_index, nn_dist, feats, fw, out);
}

// round 12
// speedup vs baseline: 1.2979x; 1.2979x over previous
#include <cuda_runtime.h>
#include <cstdint>

// Problem constants (fixed by the dataset)
#define B_    4
#define N_    8192
#define M_    2048
#define K_    32
#define C_    64
#define NBINS 16

#define MPB     4     // m-rows per block, one warp per row (warp-autonomous)
#define THREADS 128

#define G_STRIDE 20   // floats per (m,k) factor record: 16 data + 4 pad (16B-aligned)

typedef unsigned long long ull;

__device__ int g_idx_is64;

// Detect whether nn_index buffer is int64 or int32 (values < 8192 => high
// words of int64 all zero; int32 data makes odd words random). Deterministic.
__global__ void detect_idx_dtype_kernel(const int* __restrict__ words) {
    __shared__ int any_nonzero;
    if (threadIdx.x == 0) any_nonzero = 0;
    __syncthreads();
    int local = 0;
    for (int i = threadIdx.x; i < 2048; i += blockDim.x) {
        if (words[2 * i + 1] != 0) local = 1;
    }
    if (local) atomicOr(&any_nonzero, 1);
    __syncthreads();
    if (threadIdx.x == 0) g_idx_is64 = any_nonzero ? 0 : 1;
}

// Packed fp32x2 ops (Blackwell): one instruction, two fp32 lanes.
#define FMA2(d, a, b, c) \
    asm("fma.rn.f32x2 %0, %1, %2, %3;" : "=l"(d) : "l"(a), "l"(b), "l"(c))
#define MUL2(d, a, b) \
    asm("mul.rn.f32x2 %0, %1, %2;" : "=l"(d) : "l"(a), "l"(b))

__global__ __launch_bounds__(THREADS, 8) void fuzzy_sphere_kernel(
    const float* __restrict__ database,      // (B, N, 3)
    const float* __restrict__ query,         // (B, M, 3)
    const void*  __restrict__ nn_index_raw,  // (B, M, K) int64 or int32
    const float* __restrict__ nn_dist,       // (B, M, K)
    const float* __restrict__ feats,         // (B, N, C)
    const float* __restrict__ fw,            // (NBINS, C, 1)
    float* __restrict__ out)                 // (B, M, C)
{
    __shared__ float sg[MPB * K_ * G_STRIDE];  // factor records, 10 KB

    const int tid  = threadIdx.x;
    const int lane = tid & 31;
    const int wid  = tid >> 5;                 // warp id == m-row within block
    const int t2   = lane * 2;                 // channel pair base
    const int gm   = blockIdx.x * MPB + wid;   // this warp's flattened row
    const int is64 = g_idx_is64;

    // -------- Full weight table in registers: wreg[A*4 + E*2 + R] ------------
    // (bin index (A*2+E)*2+R == A*4+E*2+R, matching reference bin layout)
    ull wreg[NBINS];
    #pragma unroll
    for (int i = 0; i < NBINS; i++)
        wreg[i] = *(const ull*)(fw + i * C_ + t2);

    // ---------------- Phase 1: warp = row, lane = k --------------------------
    // Each lane emits the FACTORS of its g-vector: 4 azimuth pairs fa_A and
    // 4 elev*rad pairs t_ER (duplicated for f32x2), 64 B total.
    int off_reg;
    {
        const int k = lane;
        const int b = gm >> 11;             // gm / M_

        int nidx;
        if (is64) nidx = (int)((const long long*)nn_index_raw)[(size_t)gm * K_ + k];
        else      nidx = ((const int*)nn_index_raw)[(size_t)gm * K_ + k];

        const float d  = nn_dist[(size_t)gm * K_ + k];
        const float qx = query[gm * 3 + 0];
        const float qy = query[gm * 3 + 1];
        const float qz = query[gm * 3 + 2];
        const float* dbp = database + ((size_t)b * N_ + nidx) * 3;
        const float x = dbp[0] - qx;
        const float y = dbp[1] - qy;
        const float z = dbp[2] - qz;

        const float azimuth = atan2f(y, x) + 3.14159265358979323846f;
        float ct = z / (d + 1e-8f);
        ct = fminf(fmaxf(ct, -1.0f), 1.0f);
        const float elevation = acosf(ct);

        const float SC = 0.63661977236758134f;   // 4/(2pi) == 2/pi
        const float ab = azimuth   * SC;
        const float eb = elevation * SC;
        float rb = d / 0.05f;
        rb = fminf(fmaxf(rb, 0.0f), 2.0f - 1e-6f);

        const float afl = floorf(ab), efl = floorf(eb), rfl = floorf(rb);
        const float afr = ab - afl,   efr = eb - efl,   rfr = rb - rfl;
        const float ai = 1.0f - afr,  ei = 1.0f - efr,  ri = 1.0f - rfr;

        const int a0 = ((int)afl) & 3;
        const int ef = (int)efl;             // 0,1,(2 at poles)
        const int rf = (int)rfl;             // 0 or 1

        // Factorized axis coefficients (exact: ei+efr == 1, ri+rfr == 1)
        const float FE0 = (ef == 0) ? ei  : 0.0f;
        const float FE1 = (ef == 0) ? efr : 1.0f;
        const float FR0 = (rf == 0) ? ri  : 0.0f;
        const float FR1 = (rf == 0) ? rfr : 1.0f;

        const float t00 = FE0 * FR0, t01 = FE0 * FR1;
        const float t10 = FE1 * FR0, t11 = FE1 * FR1;

        // FA[A]: ai at a0, afr at (a0+1)&3, else 0 — no dynamic indexing
        const float fa0 = (a0 == 0) ? ai : ((a0 == 3) ? afr : 0.0f);
        const float fa1 = (a0 == 1) ? ai : ((a0 == 0) ? afr : 0.0f);
        const float fa2 = (a0 == 2) ? ai : ((a0 == 1) ? afr : 0.0f);
        const float fa3 = (a0 == 3) ? ai : ((a0 == 2) ? afr : 0.0f);

        float4* dst = (float4*)(sg + (wid * K_ + k) * G_STRIDE);
        dst[0] = make_float4(t00, t00, t01, t01);
        dst[1] = make_float4(t10, t10, t11, t11);
        dst[2] = make_float4(fa0, fa0, fa1, fa1);
        dst[3] = make_float4(fa2, fa2, fa3, fa3);

        off_reg = (b * N_ + nidx) * C_;
    }
    // Warp-internal producer/consumer only — no block barrier needed.
    __syncwarp();

    // ---------------- Phase 2: reconstruct ws from factors -------------------
    const float* mygd = sg + wid * K_ * G_STRIDE;

    ull acc = 0;                          // f32x2 (0,0)

    // 4-deep software pipeline for the gathered feature loads (offs via shfl).
    ull nfp[4];
    #pragma unroll
    for (int k = 0; k < 4; k++) {
        const int off = __shfl_sync(0xffffffffu, off_reg, k);
        nfp[k] = *(const ull*)(feats + off + t2);
    }

    #pragma unroll 4
    for (int k = 0; k < K_; k++) {
        const ull nf = nfp[k & 3];
        if (k + 4 < K_) {
            const int off = __shfl_sync(0xffffffffu, off_reg, k + 4);
            nfp[k & 3] = *(const ull*)(feats + off + t2);
        }

        // 4 broadcast LDS.128: {t00,t01},{t10,t11},{fa0,fa1},{fa2,fa3} pairs
        const ulonglong2* gp = (const ulonglong2*)(mygd + k * G_STRIDE);
        const ulonglong2 T0 = gp[0];
        const ulonglong2 T1 = gp[1];
        const ulonglong2 F0 = gp[2];
        const ulonglong2 F1 = gp[3];

        // tmp_A = sum_ER t_ER * w[A*4 + E*2 + R]   (4 independent 4-chains)
        ull tmp0, tmp1, tmp2, tmp3;
        MUL2(tmp0, T0.x, wreg[0]);
        MUL2(tmp1, T0.x, wreg[4]);
        MUL2(tmp2, T0.x, wreg[8]);
        MUL2(tmp3, T0.x, wreg[12]);
        FMA2(tmp0, T0.y, wreg[1],  tmp0);
        FMA2(tmp1, T0.y, wreg[5],  tmp1);
        FMA2(tmp2, T0.y, wreg[9],  tmp2);
        FMA2(tmp3, T0.y, wreg[13], tmp3);
        FMA2(tmp0, T1.x, wreg[2],  tmp0);
        FMA2(tmp1, T1.x, wreg[6],  tmp1);
        FMA2(tmp2, T1.x, wreg[10], tmp2);
        FMA2(tmp3, T1.x, wreg[14], tmp3);
        FMA2(tmp0, T1.y, wreg[3],  tmp0);
        FMA2(tmp1, T1.y, wreg[7],  tmp1);
        FMA2(tmp2, T1.y, wreg[11], tmp2);
        FMA2(tmp3, T1.y, wreg[15], tmp3);

        // ws = sum_A fa_A * tmp_A
        ull ws;
        MUL2(ws, F0.x, tmp0);
        FMA2(ws, F0.y, tmp1, ws);
        FMA2(ws, F1.x, tmp2, ws);
        FMA2(ws, F1.y, tmp3, ws);

        FMA2(acc, nf, ws, acc);
    }

    *(ull*)(out + (size_t)gm * C_ + t2) = acc;
}

extern "C" void kernel_launch(void* const* d_in, const int* in_sizes, int n_in,
                              void* d_out, int out_size) {
    const float* database = (const float*)d_in[0];
    const float* query    = (const float*)d_in[1];
    const void*  nn_index = (const void*) d_in[2];
    // d_in[3] = nn_count (unused by the reference einsum)
    const float* nn_dist  = (const float*)d_in[4];
    const float* feats    = (const float*)d_in[5];
    const float* fw       = (const float*)d_in[6];
    float* out = (float*)d_out;

    detect_idx_dtype_kernel<<<1, 256>>>((const int*)nn_index);

    const int blocks = (B_ * M_) / MPB;   // 2048
    fuzzy_sphere_kernel<<<blocks, THREADS>>>(
        database, query, nn_index, nn_dist, feats, fw, out);
}